// round 13
// baseline (speedup 1.0000x reference)
#include <cuda_runtime.h>
#include <cuda_bf16.h>
#include <math.h>
#include <stdint.h>

#define TB 4
#define TT 2048
#define TE 512
#define TH 8
#define TD 64
#define TBH 32
#define TU 40
#define TCAP 256
#define TM 8192
#define NSPLIT 8

// ---------------- scratch ----------------
__device__ float g_q[TBH*TT*TD];
__device__ float g_k[TBH*TT*TD];
__device__ float g_v[TBH*TT*TD];
__device__ float g_ks[TBH*TT*TD];
__device__ __nv_bfloat16 g_qh[TBH*TT*TD];
__device__ __nv_bfloat16 g_ql[TBH*TT*TD];
__device__ __nv_bfloat16 g_kh[TBH*TT*TD];
__device__ __nv_bfloat16 g_kl[TBH*TT*TD];
__device__ float g_ksum[TBH*TD];
__device__ float g_vmean[TBH*TD];
__device__ float g_statp[2*TBH*8*TD];
__device__ float g_sp[TBH*TT];
__device__ float g_s40[TBH];
__device__ int   g_cand[TBH*TCAP];
__device__ int   g_ncand[TBH];
__device__ float g_rmax[TBH*TCAP*NSPLIT];
__device__ int   g_top[TBH*TU];
__device__ float g_pm[TBH*NSPLIT*TU];
__device__ float g_ps[TBH*NSPLIT*TU];
__device__ float g_pp[TBH*NSPLIT*TU*TD];
__device__ float g_attn[TBH*TU*TD];
__device__ float g_ctx[TM*TE];
__device__ float g_base_out[TB*TE];

// ---------------- helpers ----------------
__device__ __forceinline__ uint32_t smem_u32(const void* p) {
    uint32_t a;
    asm("{ .reg .u64 t; cvta.to.shared.u64 t, %1; cvt.u32.u64 %0, t; }" : "=r"(a) : "l"(p));
    return a;
}

#define LDSM_X4(r, addr) \
    asm volatile("ldmatrix.sync.aligned.m8n8.x4.shared.b16 {%0,%1,%2,%3}, [%4];" \
        : "=r"((r)[0]),"=r"((r)[1]),"=r"((r)[2]),"=r"((r)[3]) : "r"(addr))

#define MMA_BF16(d, a, b0, b1) \
    asm volatile("mma.sync.aligned.m16n8k16.row.col.f32.bf16.bf16.f32 " \
        "{%0,%1,%2,%3}, {%4,%5,%6,%7}, {%8,%9}, {%0,%1,%2,%3};" \
        : "+f"((d)[0]),"+f"((d)[1]),"+f"((d)[2]),"+f"((d)[3]) \
        : "r"((a)[0]),"r"((a)[1]),"r"((a)[2]),"r"((a)[3]), "r"(b0),"r"(b1))

union BF2U { __nv_bfloat162 b; uint32_t u; };

__device__ __forceinline__ void split2(float x, float y, uint32_t& h, uint32_t& l) {
    BF2U hh, ll;
    hh.b = __floats2bfloat162_rn(x, y);
    float2 hf = __bfloat1622float2(hh.b);
    ll.b = __floats2bfloat162_rn(x - hf.x, y - hf.y);
    h = hh.u; l = ll.u;
}

// =====================================================================
// Kernel 1: QKV projection (R1 FFMA) + fused q bf16 split in epilogue
// =====================================================================
__global__ __launch_bounds__(256) void qkv_gemm(
    const float* __restrict__ hs,
    const float* __restrict__ Wq, const float* __restrict__ bq,
    const float* __restrict__ Wk, const float* __restrict__ bk,
    const float* __restrict__ Wv, const float* __restrict__ bv)
{
    __shared__ float As[16][132];
    __shared__ float Bs[16][132];
    const int which = blockIdx.z;
    const float* W    = (which == 0) ? Wq : (which == 1) ? Wk : Wv;
    const float* bias = (which == 0) ? bq : (which == 1) ? bk : bv;
    float* out        = (which == 0) ? g_q : (which == 1) ? g_k : g_v;
    const float scale = (which == 0) ? 0.125f : 1.0f;

    const int tid = threadIdx.x;
    const int tx = tid & 15, ty = tid >> 4;
    const int m0 = blockIdx.y * 128, n0 = blockIdx.x * 128;

    float acc[8][8];
#pragma unroll
    for (int r = 0; r < 8; r++)
#pragma unroll
        for (int c = 0; c < 8; c++) acc[r][c] = 0.f;

    for (int kt = 0; kt < 512; kt += 16) {
#pragma unroll
        for (int i = 0; i < 2; i++) {
            int l = tid + i * 256;
            int row = l >> 2, kq = l & 3;
            float4 a = *(const float4*)&hs[(size_t)(m0 + row) * 512 + kt + kq * 4];
            As[kq*4+0][row] = a.x; As[kq*4+1][row] = a.y;
            As[kq*4+2][row] = a.z; As[kq*4+3][row] = a.w;
            float4 b = *(const float4*)&W[(size_t)(n0 + row) * 512 + kt + kq * 4];
            Bs[kq*4+0][row] = b.x; Bs[kq*4+1][row] = b.y;
            Bs[kq*4+2][row] = b.z; Bs[kq*4+3][row] = b.w;
        }
        __syncthreads();
#pragma unroll
        for (int k = 0; k < 16; k++) {
            float4 a0 = *(const float4*)&As[k][ty*8];
            float4 a1 = *(const float4*)&As[k][ty*8+4];
            float4 b0 = *(const float4*)&Bs[k][tx*8];
            float4 b1 = *(const float4*)&Bs[k][tx*8+4];
            float ar[8] = {a0.x,a0.y,a0.z,a0.w,a1.x,a1.y,a1.z,a1.w};
            float br[8] = {b0.x,b0.y,b0.z,b0.w,b1.x,b1.y,b1.z,b1.w};
#pragma unroll
            for (int r = 0; r < 8; r++)
#pragma unroll
                for (int c = 0; c < 8; c++)
                    acc[r][c] = fmaf(ar[r], br[c], acc[r][c]);
        }
        __syncthreads();
    }

    const int n = n0 + tx * 8;
    const int h = n >> 6, d0 = n & 63;
#pragma unroll
    for (int r = 0; r < 8; r++) {
        int m = m0 + ty * 8 + r;
        int b = m >> 11, t = m & 2047;
        size_t ro = (size_t)(((b << 3) + h) * 2048 + t) * 64 + d0;
        float4 o0, o1;
        o0.x = (acc[r][0] + bias[n+0]) * scale;
        o0.y = (acc[r][1] + bias[n+1]) * scale;
        o0.z = (acc[r][2] + bias[n+2]) * scale;
        o0.w = (acc[r][3] + bias[n+3]) * scale;
        o1.x = (acc[r][4] + bias[n+4]) * scale;
        o1.y = (acc[r][5] + bias[n+5]) * scale;
        o1.z = (acc[r][6] + bias[n+6]) * scale;
        o1.w = (acc[r][7] + bias[n+7]) * scale;
        *(float4*)&out[ro]     = o0;
        *(float4*)&out[ro + 4] = o1;
        if (which == 0) {
            uint2 hu, lu, hu2, lu2;
            split2(o0.x, o0.y, hu.x, lu.x);
            split2(o0.z, o0.w, hu.y, lu.y);
            split2(o1.x, o1.y, hu2.x, lu2.x);
            split2(o1.z, o1.w, hu2.y, lu2.y);
            *(uint2*)&g_qh[ro]     = hu;
            *(uint2*)&g_qh[ro + 4] = hu2;
            *(uint2*)&g_ql[ro]     = lu;
            *(uint2*)&g_ql[ro + 4] = lu2;
        }
    }
}

// =====================================================================
// Kernel 2: gather sampled keys -> packed fp32 + bf16 hi/lo
// =====================================================================
__global__ __launch_bounds__(256) void gather_kernel(const int* __restrict__ idx)
{
    const int bh = blockIdx.x, jb = blockIdx.y, tid = threadIdx.x;
#pragma unroll 4
    for (int it = 0; it < 16; it++) {
        int l = it * 256 + tid;
        int jl = l >> 4, q4 = l & 15;
        int j = jb * 256 + jl;
        int ti = idx[j];
        size_t dsto = (size_t)(bh * 2048 + j) * 64 + q4 * 4;
        float4 kv = *(const float4*)&g_k[(size_t)(bh * 2048 + ti) * 64 + q4 * 4];
        *(float4*)&g_ks[dsto] = kv;
        uint2 hu, lu;
        split2(kv.x, kv.y, hu.x, lu.x);
        split2(kv.z, kv.w, hu.y, lu.y);
        *(uint2*)&g_kh[dsto] = hu;
        *(uint2*)&g_kl[dsto] = lu;
    }
}

// =====================================================================
// Kernel 3a/3b: stats partials + merge (R12, validated at 12.6us)
// =====================================================================
__global__ __launch_bounds__(256) void stats_part()
{
    __shared__ float red[4][64];
    const int bh = blockIdx.x, which = blockIdx.y, ch = blockIdx.z;
    const int tid = threadIdx.x, d = tid & 63, grp = tid >> 6;
    const float* src = ((which == 0) ? g_ks : g_v) + (size_t)bh * TT * TD;
    const int j0 = ch * 256 + grp * 64;
    float s = 0.f;
#pragma unroll 4
    for (int j = j0; j < j0 + 64; j++) s += src[(size_t)j * 64 + d];
    red[grp][d] = s;
    __syncthreads();
    if (tid < 64)
        g_statp[(((size_t)which * TBH + bh) * 8 + ch) * 64 + d] =
            (red[0][d] + red[1][d]) + (red[2][d] + red[3][d]);
}

__global__ void stats_merge()
{
    const int bh = blockIdx.x, which = blockIdx.y, d = threadIdx.x;
    const float* p = &g_statp[(((size_t)which * TBH + bh) * 8) * 64 + d];
    float s = 0.f;
#pragma unroll
    for (int c = 0; c < 8; c++) s += p[(size_t)c * 64];
    if (which == 0) g_ksum[bh * 64 + d] = s;
    else            g_vmean[bh * 64 + d] = s * (1.0f / 2048.0f);
}

// =====================================================================
// Kernel 4: APPROXIMATE sparsity via bf16 2-split 3-term mma.sync
// =====================================================================
__global__ __launch_bounds__(256) void sparsity_mma()
{
    extern __shared__ __align__(16) __nv_bfloat16 dynsm[];
    __nv_bfloat16* Qh = dynsm;
    __nv_bfloat16* Ql = dynsm + 9216;
    __nv_bfloat16* Kh = dynsm + 18432;
    __nv_bfloat16* Kl = dynsm + 27648;
    float* red = (float*)(dynsm + 36864);

    const int tid = threadIdx.x, wid = tid >> 5, lane = tid & 31;
    const int wm = wid >> 1, wn = wid & 1;
    const int m0 = blockIdx.x * 128, bh = blockIdx.y;

    const __nv_bfloat16* gqh = g_qh + (size_t)bh * TT * TD;
    const __nv_bfloat16* gql = g_ql + (size_t)bh * TT * TD;
    const __nv_bfloat16* gkh = g_kh + (size_t)bh * TT * TD;
    const __nv_bfloat16* gkl = g_kl + (size_t)bh * TT * TD;

#pragma unroll
    for (int i = 0; i < 4; i++) {
        int l = tid + i * 256;
        int row = l >> 3, seg = l & 7;
        *(uint4*)&Qh[row*72 + seg*8] = *(const uint4*)&gqh[(size_t)(m0+row)*64 + seg*8];
        *(uint4*)&Ql[row*72 + seg*8] = *(const uint4*)&gql[(size_t)(m0+row)*64 + seg*8];
    }

    const int arow = wm * 32 + (lane & 15);
    const int acol8 = (lane >> 4) << 3;
    const int brow = wn * 64 + (lane & 7) + ((lane >> 4) << 3);
    const int bk8 = ((lane >> 3) & 1) << 3;

    float rmax[2][2];
    rmax[0][0] = rmax[0][1] = rmax[1][0] = rmax[1][1] = -INFINITY;

    for (int nt = 0; nt < 16; nt++) {
        __syncthreads();
        const size_t n0 = (size_t)nt * 128;
#pragma unroll
        for (int i = 0; i < 4; i++) {
            int l = tid + i * 256;
            int row = l >> 3, seg = l & 7;
            *(uint4*)&Kh[row*72 + seg*8] = *(const uint4*)&gkh[(n0+row)*64 + seg*8];
            *(uint4*)&Kl[row*72 + seg*8] = *(const uint4*)&gkl[(n0+row)*64 + seg*8];
        }
        __syncthreads();

        float acc[2][8][4];
#pragma unroll
        for (int a = 0; a < 2; a++)
#pragma unroll
            for (int b = 0; b < 8; b++)
#pragma unroll
                for (int c = 0; c < 4; c++) acc[a][b][c] = 0.f;

#pragma unroll
        for (int kc = 0; kc < 64; kc += 16) {
            uint32_t ah[2][4], al[2][4];
#pragma unroll
            for (int mi = 0; mi < 2; mi++) {
                LDSM_X4(ah[mi], smem_u32(&Qh[(arow + mi*16)*72 + kc + acol8]));
                LDSM_X4(al[mi], smem_u32(&Ql[(arow + mi*16)*72 + kc + acol8]));
            }
#pragma unroll
            for (int nb = 0; nb < 4; nb++) {
                uint32_t bh4[4], bl4[4];
                LDSM_X4(bh4, smem_u32(&Kh[(brow + nb*16)*72 + kc + bk8]));
                LDSM_X4(bl4, smem_u32(&Kl[(brow + nb*16)*72 + kc + bk8]));
#pragma unroll
                for (int mi = 0; mi < 2; mi++) {
                    MMA_BF16(acc[mi][nb*2+0], ah[mi], bh4[0], bh4[1]);
                    MMA_BF16(acc[mi][nb*2+1], ah[mi], bh4[2], bh4[3]);
                    MMA_BF16(acc[mi][nb*2+0], ah[mi], bl4[0], bl4[1]);
                    MMA_BF16(acc[mi][nb*2+1], ah[mi], bl4[2], bl4[3]);
                    MMA_BF16(acc[mi][nb*2+0], al[mi], bh4[0], bh4[1]);
                    MMA_BF16(acc[mi][nb*2+1], al[mi], bh4[2], bh4[3]);
                }
            }
        }
#pragma unroll
        for (int mi = 0; mi < 2; mi++)
#pragma unroll
            for (int nf = 0; nf < 8; nf++) {
                rmax[mi][0] = fmaxf(rmax[mi][0], fmaxf(acc[mi][nf][0], acc[mi][nf][1]));
                rmax[mi][1] = fmaxf(rmax[mi][1], fmaxf(acc[mi][nf][2], acc[mi][nf][3]));
            }
    }

#pragma unroll
    for (int mi = 0; mi < 2; mi++)
#pragma unroll
        for (int hf = 0; hf < 2; hf++) {
            float v = rmax[mi][hf];
            v = fmaxf(v, __shfl_xor_sync(0xffffffff, v, 1));
            v = fmaxf(v, __shfl_xor_sync(0xffffffff, v, 2));
            if ((lane & 3) == 0)
                red[wn * 128 + wm * 32 + mi * 16 + hf * 8 + (lane >> 2)] = v;
        }
    __syncthreads();

    if (tid < 128) {
        float m = fmaxf(red[tid], red[128 + tid]);
        const float* qr = g_q + ((size_t)bh * TT + m0 + tid) * 64;
        const float* ks = g_ksum + bh * 64;
        float dot = 0.f;
#pragma unroll
        for (int d = 0; d < 64; d++) dot = fmaf(qr[d], ks[d], dot);
        g_sp[bh * TT + m0 + tid] = m - dot * (1.0f / 2048.0f);
    }
}

// =====================================================================
// Kernel 5: approx 40th-largest sparsity per bh
// =====================================================================
__global__ __launch_bounds__(256) void topk40_kernel()
{
    __shared__ float sp[2048];
    __shared__ float rv[256];
    __shared__ int   ri[256];
    const int bh = blockIdx.x, tid = threadIdx.x;
    for (int l = tid; l < 2048; l += 256) sp[l] = g_sp[bh * 2048 + l];
    __syncthreads();
    for (int it = 0; it < TU; it++) {
        float bv = -INFINITY; int bi = 2048;
        for (int l = tid; l < 2048; l += 256) {
            float v = sp[l];
            if (v > bv) { bv = v; bi = l; }
        }
        rv[tid] = bv; ri[tid] = bi;
        __syncthreads();
        for (int s = 128; s > 0; s >>= 1) {
            if (tid < s) {
                float ov = rv[tid + s]; int oi = ri[tid + s];
                if (ov > rv[tid] || (ov == rv[tid] && oi < ri[tid])) { rv[tid] = ov; ri[tid] = oi; }
            }
            __syncthreads();
        }
        if (tid == 0) {
            sp[ri[0]] = -INFINITY;
            if (it == TU - 1) g_s40[bh] = rv[0];
        }
        __syncthreads();
    }
}

// =====================================================================
// Kernel 5b: collect candidates with approx score >= s40 - delta
// =====================================================================
__global__ __launch_bounds__(256) void cand_kernel()
{
    __shared__ int cnt;
    const int bh = blockIdx.x, tid = threadIdx.x;
    if (tid == 0) cnt = 0;
    __syncthreads();
    const float thr = g_s40[bh] - 0.02f;
    for (int l = tid; l < 2048; l += 256) {
        if (g_sp[bh * 2048 + l] >= thr) {
            int p = atomicAdd(&cnt, 1);
            if (p < TCAP) g_cand[bh * TCAP + p] = l;
        }
    }
    __syncthreads();
    if (tid == 0) g_ncand[bh] = (cnt < TCAP) ? cnt : TCAP;
}

// =====================================================================
// Kernel 5c: exact fp32 rescore of candidates
// =====================================================================
__global__ __launch_bounds__(256) void rescore_kernel()
{
    __shared__ float qc[64][68];
    __shared__ float ks[32][68];
    const int bh = blockIdx.x, sp = blockIdx.y, tid = threadIdx.x;
    const int ncand = g_ncand[bh];
    const int c = tid >> 2, l4 = tid & 3;

    for (int c0 = 0; c0 < ncand; c0 += 64) {
        const int nc = min(64, ncand - c0);
        __syncthreads();
        for (int l = tid; l < nc * 16; l += 256) {
            int cc = l >> 4, q4 = l & 15;
            int t = g_cand[bh * TCAP + c0 + cc];
            *(float4*)&qc[cc][q4*4] = *(const float4*)&g_q[((size_t)bh * 2048 + t) * 64 + q4 * 4];
        }
        float m = -INFINITY;
        for (int ch = 0; ch < 8; ch++) {
            const int j0 = sp * 256 + ch * 32;
            __syncthreads();
            for (int l = tid; l < 512; l += 256) {
                int j = l >> 4, q4 = l & 15;
                *(float4*)&ks[j][q4*4] = *(const float4*)&g_ks[((size_t)bh * 2048 + j0 + j) * 64 + q4 * 4];
            }
            __syncthreads();
            if (c < nc) {
#pragma unroll
                for (int kk = 0; kk < 8; kk++) {
                    int j = l4 + kk * 4;
                    float dot = 0.f;
#pragma unroll
                    for (int d = 0; d < 64; d++) dot = fmaf(qc[c][d], ks[j][d], dot);
                    m = fmaxf(m, dot);
                }
            }
        }
        m = fmaxf(m, __shfl_xor_sync(0xffffffff, m, 1));
        m = fmaxf(m, __shfl_xor_sync(0xffffffff, m, 2));
        if (l4 == 0 && c < nc)
            g_rmax[(bh * TCAP + c0 + c) * NSPLIT + sp] = m;
    }
}

// =====================================================================
// Kernel 5d: exact candidate sparsity + exact top-40 (tie: lower t)
// =====================================================================
__global__ __launch_bounds__(256) void final_topk_kernel()
{
    __shared__ float sv[256];
    __shared__ int   st[256];
    __shared__ float rv[256];
    __shared__ int   rs[256];
    __shared__ float sks[64];
    const int bh = blockIdx.x, tid = threadIdx.x;
    const int ncand = g_ncand[bh];
    if (tid < 64) sks[tid] = g_ksum[bh * 64 + tid];
    __syncthreads();

    float val = -INFINITY;
    int t = 0x7fffffff;
    if (tid < ncand) {
        t = g_cand[bh * TCAP + tid];
        float m = -INFINITY;
#pragma unroll
        for (int sp = 0; sp < NSPLIT; sp++)
            m = fmaxf(m, g_rmax[(bh * TCAP + tid) * NSPLIT + sp]);
        const float* qr = g_q + ((size_t)bh * 2048 + t) * 64;
        float dot = 0.f;
#pragma unroll
        for (int d = 0; d < 64; d++) dot = fmaf(qr[d], sks[d], dot);
        val = m - dot * (1.0f / 2048.0f);
    }
    sv[tid] = val; st[tid] = t;
    __syncthreads();

    for (int it = 0; it < TU; it++) {
        rv[tid] = sv[tid]; rs[tid] = tid;
        __syncthreads();
        for (int s = 128; s > 0; s >>= 1) {
            if (tid < s) {
                float ov = rv[tid + s]; int os = rs[tid + s];
                if (ov > rv[tid] || (ov == rv[tid] && st[os] < st[rs[tid]])) { rv[tid] = ov; rs[tid] = os; }
            }
            __syncthreads();
        }
        if (tid == 0) { g_top[bh * TU + it] = st[rs[0]]; sv[rs[0]] = -INFINITY; }
        __syncthreads();
    }
}

// =====================================================================
// Kernel 6: FUSED flash-style attention over 256-key chunks (R12)
// =====================================================================
#define SM_QS 0
#define SM_KV (40*68)
#define SM_E  (40*68 + 64*68)
#define SM_M  (SM_E + 40*256)
#define SM_S  (SM_M + 40)
#define SM_TOT (SM_S + 40)

__global__ __launch_bounds__(256) void attn_fused()
{
    extern __shared__ __align__(16) float fs[];
    const int sp = blockIdx.x, bh = blockIdx.y, tid = threadIdx.x;
    const int j = tid & 63, ig = tid >> 6;

    for (int l = tid; l < 640; l += 256) {
        int i = l >> 4, q4 = l & 15;
        int t = g_top[bh * TU + i];
        *(float4*)&fs[SM_QS + i*68 + q4*4] =
            *(const float4*)&g_q[((size_t)bh * 2048 + t) * 64 + q4 * 4];
    }

    for (int c = 0; c < 4; c++) {
        const int j0 = sp * 256 + c * 64;
        __syncthreads();
        for (int l = tid; l < 1024; l += 256) {
            int jj = l >> 4, q4 = l & 15;
            *(float4*)&fs[SM_KV + jj*68 + q4*4] =
                *(const float4*)&g_k[((size_t)bh * 2048 + j0 + jj) * 64 + q4 * 4];
        }
        __syncthreads();
#pragma unroll
        for (int r = 0; r < 10; r++) {
            const int i = ig * 10 + r;
            float dot = 0.f;
#pragma unroll
            for (int d = 0; d < 64; d++)
                dot = fmaf(fs[SM_QS + i*68 + d], fs[SM_KV + j*68 + d], dot);
            fs[SM_E + i*256 + c*64 + j] = dot;
        }
    }
    __syncthreads();

    if (tid < 40) {
        float m = -INFINITY;
        for (int jj = 0; jj < 256; jj++) m = fmaxf(m, fs[SM_E + tid*256 + jj]);
        fs[SM_M + tid] = m;
    }
    __syncthreads();
    for (int l = tid; l < 10240; l += 256) {
        int i = l >> 8;
        fs[SM_E + l] = expf(fs[SM_E + l] - fs[SM_M + i]);
    }
    __syncthreads();
    if (tid < 40) {
        float s = 0.f;
        for (int jj = 0; jj < 256; jj++) s += fs[SM_E + tid*256 + jj];
        g_pm[(bh * NSPLIT + sp) * TU + tid] = fs[SM_M + tid];
        g_ps[(bh * NSPLIT + sp) * TU + tid] = s;
    }

    float acc[10];
#pragma unroll
    for (int r = 0; r < 10; r++) acc[r] = 0.f;
    for (int c = 0; c < 4; c++) {
        const int j0 = sp * 256 + c * 64;
        __syncthreads();
        for (int l = tid; l < 1024; l += 256) {
            int jj = l >> 4, q4 = l & 15;
            *(float4*)&fs[SM_KV + jj*68 + q4*4] =
                *(const float4*)&g_v[((size_t)bh * 2048 + j0 + jj) * 64 + q4 * 4];
        }
        __syncthreads();
#pragma unroll 4
        for (int jj = 0; jj < 64; jj++) {
            float vv = fs[SM_KV + jj*68 + j];
#pragma unroll
            for (int r = 0; r < 10; r++)
                acc[r] = fmaf(fs[SM_E + (ig*10 + r)*256 + c*64 + jj], vv, acc[r]);
        }
    }
#pragma unroll
    for (int r = 0; r < 10; r++)
        g_pp[((size_t)(bh * NSPLIT + sp) * TU + ig * 10 + r) * 64 + j] = acc[r];
}

__global__ __launch_bounds__(256) void attn_merge()
{
    const int bh = blockIdx.x, tid = threadIdx.x;
    const int d = tid & 63, ii = tid >> 6;
#pragma unroll
    for (int r = 0; r < 10; r++) {
        const int i = ii * 10 + r;
        float M = -INFINITY;
#pragma unroll
        for (int k = 0; k < NSPLIT; k++)
            M = fmaxf(M, g_pm[(bh * NSPLIT + k) * TU + i]);
        float S = 0.f, o = 0.f;
#pragma unroll
        for (int k = 0; k < NSPLIT; k++) {
            float w = expf(g_pm[(bh * NSPLIT + k) * TU + i] - M);
            S = fmaf(g_ps[(bh * NSPLIT + k) * TU + i], w, S);
            o = fmaf(g_pp[((size_t)(bh * NSPLIT + k) * TU + i) * 64 + d], w, o);
        }
        g_attn[(bh * TU + i) * 64 + d] = o / S;
    }
}

// =====================================================================
// Kernel 9: fill merged context with vmean
// =====================================================================
__global__ __launch_bounds__(256) void ctxfill_kernel()
{
    const int idx = blockIdx.x * 256 + threadIdx.x;
    const int m = idx >> 7, nf4 = idx & 127;
    const int b = m >> 11;
    const int h = nf4 >> 4, d0 = (nf4 & 15) * 4;
    float4 v = *(const float4*)&g_vmean[((b << 3) + h) * 64 + d0];
    *(float4*)&g_ctx[(size_t)m * 512 + nf4 * 4] = v;
}

// =====================================================================
// Kernel 10: scatter attention rows into context
// =====================================================================
__global__ void scatter_kernel()
{
    const int bh = blockIdx.x, i = blockIdx.y, d = threadIdx.x;
    const int t = g_top[bh * TU + i];
    const int b = bh >> 3, h = bh & 7;
    g_ctx[(size_t)((b << 11) + t) * 512 + (h << 6) + d] =
        g_attn[(bh * TU + i) * 64 + d];
}

// =====================================================================
// Kernel 11a: base_out[b] = bo + vmean_ctx_row(b) @ Wo^T (GEMV)
// =====================================================================
__global__ __launch_bounds__(128) void base_prep(
    const float* __restrict__ Wo, const float* __restrict__ bo)
{
    __shared__ float bs[512];
    const int b = blockIdx.x, n0 = blockIdx.y * 128, tid = threadIdx.x;
    for (int k = tid; k < 512; k += 128) bs[k] = g_vmean[b * 512 + k];
    __syncthreads();
    const int n = n0 + tid;
    const float* w = Wo + (size_t)n * 512;
    float acc = bo[n];
#pragma unroll 8
    for (int k = 0; k < 512; k++) acc = fmaf(bs[k], w[k], acc);
    g_base_out[b * 512 + n] = acc;
}

// =====================================================================
// Kernel 11b: broadcast-fill output with per-batch base rows
// =====================================================================
__global__ __launch_bounds__(256) void fill_out(float* __restrict__ out)
{
    const int idx = blockIdx.x * 256 + threadIdx.x;
    const int m = idx >> 7, nf4 = idx & 127;
    const int b = m >> 11;
    float4 v = *(const float4*)&g_base_out[b * 512 + nf4 * 4];
    *(float4*)&out[(size_t)m * 512 + nf4 * 4] = v;
}

// =====================================================================
// Kernel 11c: compact output GEMM over the 1280 modified ctx rows.
// Proven 128x128x16 tile; A rows gathered via g_top; epilogue writes
// mapped out rows. Duplicate (b,t) rows write identical values.
// =====================================================================
__global__ __launch_bounds__(256) void out_gemm_compact(
    const float* __restrict__ Wo, const float* __restrict__ bo,
    float* __restrict__ out)
{
    __shared__ float As[16][132];
    __shared__ float Bs[16][132];
    __shared__ int rowoff[128];     // (b*2048 + t) per tile row
    const int tid = threadIdx.x;
    const int tx = tid & 15, ty = tid >> 4;
    const int m0 = blockIdx.y * 128, n0 = blockIdx.x * 128;

    if (tid < 128) {
        int mr = m0 + tid;           // slot index in [0, 1280)
        int bh = mr / TU, i = mr % TU;
        int t = g_top[bh * TU + i];
        rowoff[tid] = ((bh >> 3) << 11) + t;
    }
    __syncthreads();

    float acc[8][8];
#pragma unroll
    for (int r = 0; r < 8; r++)
#pragma unroll
        for (int c = 0; c < 8; c++) acc[r][c] = 0.f;

    for (int kt = 0; kt < 512; kt += 16) {
#pragma unroll
        for (int i = 0; i < 2; i++) {
            int l = tid + i * 256;
            int row = l >> 2, kq = l & 3;
            float4 a = *(const float4*)&g_ctx[(size_t)rowoff[row] * 512 + kt + kq * 4];
            As[kq*4+0][row] = a.x; As[kq*4+1][row] = a.y;
            As[kq*4+2][row] = a.z; As[kq*4+3][row] = a.w;
            float4 b = *(const float4*)&Wo[(size_t)(n0 + row) * 512 + kt + kq * 4];
            Bs[kq*4+0][row] = b.x; Bs[kq*4+1][row] = b.y;
            Bs[kq*4+2][row] = b.z; Bs[kq*4+3][row] = b.w;
        }
        __syncthreads();
#pragma unroll
        for (int k = 0; k < 16; k++) {
            float4 a0 = *(const float4*)&As[k][ty*8];
            float4 a1 = *(const float4*)&As[k][ty*8+4];
            float4 b0 = *(const float4*)&Bs[k][tx*8];
            float4 b1 = *(const float4*)&Bs[k][tx*8+4];
            float ar[8] = {a0.x,a0.y,a0.z,a0.w,a1.x,a1.y,a1.z,a1.w};
            float br[8] = {b0.x,b0.y,b0.z,b0.w,b1.x,b1.y,b1.z,b1.w};
#pragma unroll
            for (int r = 0; r < 8; r++)
#pragma unroll
                for (int c = 0; c < 8; c++)
                    acc[r][c] = fmaf(ar[r], br[c], acc[r][c]);
        }
        __syncthreads();
    }

    const int n = n0 + tx * 8;
#pragma unroll
    for (int r = 0; r < 8; r++) {
        int row = ty * 8 + r;
        float* orow = &out[(size_t)rowoff[row] * 512 + n];
        float4 o0, o1;
        o0.x = acc[r][0] + bo[n+0]; o0.y = acc[r][1] + bo[n+1];
        o0.z = acc[r][2] + bo[n+2]; o0.w = acc[r][3] + bo[n+3];
        o1.x = acc[r][4] + bo[n+4]; o1.y = acc[r][5] + bo[n+5];
        o1.z = acc[r][6] + bo[n+6]; o1.w = acc[r][7] + bo[n+7];
        *(float4*)&orow[0] = o0;
        *(float4*)&orow[4] = o1;
    }
}

// =====================================================================
extern "C" void kernel_launch(void* const* d_in, const int* in_sizes, int n_in,
                              void* d_out, int out_size)
{
    const float* hs = (const float*)d_in[0];
    const int*  idx = (const int*)  d_in[1];
    const float* Wq = (const float*)d_in[2]; const float* bq = (const float*)d_in[3];
    const float* Wk = (const float*)d_in[4]; const float* bk = (const float*)d_in[5];
    const float* Wv = (const float*)d_in[6]; const float* bv = (const float*)d_in[7];
    const float* Wo = (const float*)d_in[8]; const float* bo = (const float*)d_in[9];
    float* out = (float*)d_out;

    cudaFuncSetAttribute(sparsity_mma, cudaFuncAttributeMaxDynamicSharedMemorySize, 75776);
    cudaFuncSetAttribute(attn_fused, cudaFuncAttributeMaxDynamicSharedMemorySize, SM_TOT * 4);

    qkv_gemm     <<<dim3(4, 64, 3), 256>>>(hs, Wq, bq, Wk, bk, Wv, bv);
    gather_kernel<<<dim3(32, 8), 256>>>(idx);
    stats_part   <<<dim3(32, 2, 8), 256>>>();
    stats_merge  <<<dim3(32, 2), 64>>>();
    sparsity_mma <<<dim3(16, 32), 256, 75776>>>();
    topk40_kernel<<<32, 256>>>();
    cand_kernel  <<<32, 256>>>();
    rescore_kernel<<<dim3(32, NSPLIT), 256>>>();
    final_topk_kernel<<<32, 256>>>();
    attn_fused   <<<dim3(NSPLIT, 32), 256, SM_TOT * 4>>>();
    attn_merge   <<<32, 256>>>();
    ctxfill_kernel<<<4096, 256>>>();
    scatter_kernel<<<dim3(32, TU), 64>>>();
    base_prep    <<<dim3(TB, 4), 128>>>(Wo, bo);
    fill_out     <<<4096, 256>>>(out);
    out_gemm_compact<<<dim3(4, 10), 256>>>(Wo, bo, out);
}

// round 14
// speedup vs baseline: 1.0728x; 1.0728x over previous
#include <cuda_runtime.h>
#include <cuda_fp16.h>
#include <math.h>
#include <stdint.h>

#define TB 4
#define TT 2048
#define TE 512
#define TH 8
#define TD 64
#define TBH 32
#define TU 40
#define TCAP 512
#define TM 8192
#define NSPLIT 8

// ---------------- scratch ----------------
__device__ float g_q[TBH*TT*TD];
__device__ float g_k[TBH*TT*TD];
__device__ float g_v[TBH*TT*TD];
__device__ float g_ks[TBH*TT*TD];
__device__ __half g_qh[TBH*TT*TD];     // fp16 q (prefilter)
__device__ __half g_kh[TBH*TT*TD];     // fp16 k_sample (prefilter)
__device__ float g_ksum[TBH*TD];
__device__ float g_vmean[TBH*TD];
__device__ float g_statp[2*TBH*8*TD];
__device__ float g_sp[TBH*TT];
__device__ float g_s40[TBH];
__device__ int   g_cand[TBH*TCAP];
__device__ int   g_ncand[TBH];
__device__ float g_rmax[TBH*TCAP*NSPLIT];
__device__ int   g_top[TBH*TU];
__device__ float g_pm[TBH*NSPLIT*TU];
__device__ float g_ps[TBH*NSPLIT*TU];
__device__ float g_pp[TBH*NSPLIT*TU*TD];
__device__ float g_attn[TBH*TU*TD];
__device__ float g_ctx[TM*TE];
__device__ float g_base_out[TB*TE];

// ---------------- helpers ----------------
__device__ __forceinline__ uint32_t smem_u32(const void* p) {
    uint32_t a;
    asm("{ .reg .u64 t; cvta.to.shared.u64 t, %1; cvt.u32.u64 %0, t; }" : "=r"(a) : "l"(p));
    return a;
}

#define LDSM_X4(r, addr) \
    asm volatile("ldmatrix.sync.aligned.m8n8.x4.shared.b16 {%0,%1,%2,%3}, [%4];" \
        : "=r"((r)[0]),"=r"((r)[1]),"=r"((r)[2]),"=r"((r)[3]) : "r"(addr))

#define MMA_FP16(d, a, b0, b1) \
    asm volatile("mma.sync.aligned.m16n8k16.row.col.f32.f16.f16.f32 " \
        "{%0,%1,%2,%3}, {%4,%5,%6,%7}, {%8,%9}, {%0,%1,%2,%3};" \
        : "+f"((d)[0]),"+f"((d)[1]),"+f"((d)[2]),"+f"((d)[3]) \
        : "r"((a)[0]),"r"((a)[1]),"r"((a)[2]),"r"((a)[3]), "r"(b0),"r"(b1))

union H2U { __half2 h; uint32_t u; };

__device__ __forceinline__ uint32_t pack_h2(float x, float y) {
    H2U u; u.h = __floats2half2_rn(x, y); return u.u;
}

// =====================================================================
// Kernel 1: QKV projection (R1 FFMA) + fused q fp16 write in epilogue
// =====================================================================
__global__ __launch_bounds__(256) void qkv_gemm(
    const float* __restrict__ hs,
    const float* __restrict__ Wq, const float* __restrict__ bq,
    const float* __restrict__ Wk, const float* __restrict__ bk,
    const float* __restrict__ Wv, const float* __restrict__ bv)
{
    __shared__ float As[16][132];
    __shared__ float Bs[16][132];
    const int which = blockIdx.z;
    const float* W    = (which == 0) ? Wq : (which == 1) ? Wk : Wv;
    const float* bias = (which == 0) ? bq : (which == 1) ? bk : bv;
    float* out        = (which == 0) ? g_q : (which == 1) ? g_k : g_v;
    const float scale = (which == 0) ? 0.125f : 1.0f;

    const int tid = threadIdx.x;
    const int tx = tid & 15, ty = tid >> 4;
    const int m0 = blockIdx.y * 128, n0 = blockIdx.x * 128;

    float acc[8][8];
#pragma unroll
    for (int r = 0; r < 8; r++)
#pragma unroll
        for (int c = 0; c < 8; c++) acc[r][c] = 0.f;

    for (int kt = 0; kt < 512; kt += 16) {
#pragma unroll
        for (int i = 0; i < 2; i++) {
            int l = tid + i * 256;
            int row = l >> 2, kq = l & 3;
            float4 a = *(const float4*)&hs[(size_t)(m0 + row) * 512 + kt + kq * 4];
            As[kq*4+0][row] = a.x; As[kq*4+1][row] = a.y;
            As[kq*4+2][row] = a.z; As[kq*4+3][row] = a.w;
            float4 b = *(const float4*)&W[(size_t)(n0 + row) * 512 + kt + kq * 4];
            Bs[kq*4+0][row] = b.x; Bs[kq*4+1][row] = b.y;
            Bs[kq*4+2][row] = b.z; Bs[kq*4+3][row] = b.w;
        }
        __syncthreads();
#pragma unroll
        for (int k = 0; k < 16; k++) {
            float4 a0 = *(const float4*)&As[k][ty*8];
            float4 a1 = *(const float4*)&As[k][ty*8+4];
            float4 b0 = *(const float4*)&Bs[k][tx*8];
            float4 b1 = *(const float4*)&Bs[k][tx*8+4];
            float ar[8] = {a0.x,a0.y,a0.z,a0.w,a1.x,a1.y,a1.z,a1.w};
            float br[8] = {b0.x,b0.y,b0.z,b0.w,b1.x,b1.y,b1.z,b1.w};
#pragma unroll
            for (int r = 0; r < 8; r++)
#pragma unroll
                for (int c = 0; c < 8; c++)
                    acc[r][c] = fmaf(ar[r], br[c], acc[r][c]);
        }
        __syncthreads();
    }

    const int n = n0 + tx * 8;
    const int h = n >> 6, d0 = n & 63;
#pragma unroll
    for (int r = 0; r < 8; r++) {
        int m = m0 + ty * 8 + r;
        int b = m >> 11, t = m & 2047;
        size_t ro = (size_t)(((b << 3) + h) * 2048 + t) * 64 + d0;
        float4 o0, o1;
        o0.x = (acc[r][0] + bias[n+0]) * scale;
        o0.y = (acc[r][1] + bias[n+1]) * scale;
        o0.z = (acc[r][2] + bias[n+2]) * scale;
        o0.w = (acc[r][3] + bias[n+3]) * scale;
        o1.x = (acc[r][4] + bias[n+4]) * scale;
        o1.y = (acc[r][5] + bias[n+5]) * scale;
        o1.z = (acc[r][6] + bias[n+6]) * scale;
        o1.w = (acc[r][7] + bias[n+7]) * scale;
        *(float4*)&out[ro]     = o0;
        *(float4*)&out[ro + 4] = o1;
        if (which == 0) {
            uint4 hp;
            hp.x = pack_h2(o0.x, o0.y);
            hp.y = pack_h2(o0.z, o0.w);
            hp.z = pack_h2(o1.x, o1.y);
            hp.w = pack_h2(o1.z, o1.w);
            *(uint4*)&g_qh[ro] = hp;
        }
    }
}

// =====================================================================
// Kernel 2: gather sampled keys -> packed fp32 + fp16
// =====================================================================
__global__ __launch_bounds__(256) void gather_kernel(const int* __restrict__ idx)
{
    const int bh = blockIdx.x, jb = blockIdx.y, tid = threadIdx.x;
#pragma unroll 4
    for (int it = 0; it < 16; it++) {
        int l = it * 256 + tid;
        int jl = l >> 4, q4 = l & 15;
        int j = jb * 256 + jl;
        int ti = idx[j];
        size_t dsto = (size_t)(bh * 2048 + j) * 64 + q4 * 4;
        float4 kv = *(const float4*)&g_k[(size_t)(bh * 2048 + ti) * 64 + q4 * 4];
        *(float4*)&g_ks[dsto] = kv;
        uint2 hp;
        hp.x = pack_h2(kv.x, kv.y);
        hp.y = pack_h2(kv.z, kv.w);
        *(uint2*)&g_kh[dsto] = hp;
    }
}

// =====================================================================
// Kernel 3a/3b: stats partials + merge (validated 12.6us)
// =====================================================================
__global__ __launch_bounds__(256) void stats_part()
{
    __shared__ float red[4][64];
    const int bh = blockIdx.x, which = blockIdx.y, ch = blockIdx.z;
    const int tid = threadIdx.x, d = tid & 63, grp = tid >> 6;
    const float* src = ((which == 0) ? g_ks : g_v) + (size_t)bh * TT * TD;
    const int j0 = ch * 256 + grp * 64;
    float s = 0.f;
#pragma unroll 4
    for (int j = j0; j < j0 + 64; j++) s += src[(size_t)j * 64 + d];
    red[grp][d] = s;
    __syncthreads();
    if (tid < 64)
        g_statp[(((size_t)which * TBH + bh) * 8 + ch) * 64 + d] =
            (red[0][d] + red[1][d]) + (red[2][d] + red[3][d]);
}

__global__ void stats_merge()
{
    const int bh = blockIdx.x, which = blockIdx.y, d = threadIdx.x;
    const float* p = &g_statp[(((size_t)which * TBH + bh) * 8) * 64 + d];
    float s = 0.f;
#pragma unroll
    for (int c = 0; c < 8; c++) s += p[(size_t)c * 64];
    if (which == 0) g_ksum[bh * 64 + d] = s;
    else            g_vmean[bh * 64 + d] = s * (1.0f / 2048.0f);
}

// =====================================================================
// Kernel 4: APPROXIMATE sparsity via SINGLE-term fp16 mma.sync.
// Error <= ~5e-3 << delta=0.05. Prefilter only.
// =====================================================================
__global__ __launch_bounds__(256) void sparsity_mma()
{
    extern __shared__ __align__(16) __half dynsm[];
    __half* Qh = dynsm;                  // [128][72]
    __half* Kh = dynsm + 9216;           // [128][72]
    float* red = (float*)(dynsm + 18432);  // [2][128]

    const int tid = threadIdx.x, wid = tid >> 5, lane = tid & 31;
    const int wm = wid >> 1, wn = wid & 1;
    const int m0 = blockIdx.x * 128, bh = blockIdx.y;

    const __half* gqh = g_qh + (size_t)bh * TT * TD;
    const __half* gkh = g_kh + (size_t)bh * TT * TD;

#pragma unroll
    for (int i = 0; i < 4; i++) {
        int l = tid + i * 256;
        int row = l >> 3, seg = l & 7;
        *(uint4*)&Qh[row*72 + seg*8] = *(const uint4*)&gqh[(size_t)(m0+row)*64 + seg*8];
    }

    const int arow = wm * 32 + (lane & 15);
    const int acol8 = (lane >> 4) << 3;
    const int brow = wn * 64 + (lane & 7) + ((lane >> 4) << 3);
    const int bk8 = ((lane >> 3) & 1) << 3;

    float rmax[2][2];
    rmax[0][0] = rmax[0][1] = rmax[1][0] = rmax[1][1] = -INFINITY;

    for (int nt = 0; nt < 16; nt++) {
        __syncthreads();
        const size_t n0 = (size_t)nt * 128;
#pragma unroll
        for (int i = 0; i < 4; i++) {
            int l = tid + i * 256;
            int row = l >> 3, seg = l & 7;
            *(uint4*)&Kh[row*72 + seg*8] = *(const uint4*)&gkh[(n0+row)*64 + seg*8];
        }
        __syncthreads();

        float acc[2][8][4];
#pragma unroll
        for (int a = 0; a < 2; a++)
#pragma unroll
            for (int b = 0; b < 8; b++)
#pragma unroll
                for (int c = 0; c < 4; c++) acc[a][b][c] = 0.f;

#pragma unroll
        for (int kc = 0; kc < 64; kc += 16) {
            uint32_t ah[2][4];
#pragma unroll
            for (int mi = 0; mi < 2; mi++)
                LDSM_X4(ah[mi], smem_u32(&Qh[(arow + mi*16)*72 + kc + acol8]));
#pragma unroll
            for (int nb = 0; nb < 4; nb++) {
                uint32_t bh4[4];
                LDSM_X4(bh4, smem_u32(&Kh[(brow + nb*16)*72 + kc + bk8]));
#pragma unroll
                for (int mi = 0; mi < 2; mi++) {
                    MMA_FP16(acc[mi][nb*2+0], ah[mi], bh4[0], bh4[1]);
                    MMA_FP16(acc[mi][nb*2+1], ah[mi], bh4[2], bh4[3]);
                }
            }
        }
#pragma unroll
        for (int mi = 0; mi < 2; mi++)
#pragma unroll
            for (int nf = 0; nf < 8; nf++) {
                rmax[mi][0] = fmaxf(rmax[mi][0], fmaxf(acc[mi][nf][0], acc[mi][nf][1]));
                rmax[mi][1] = fmaxf(rmax[mi][1], fmaxf(acc[mi][nf][2], acc[mi][nf][3]));
            }
    }

#pragma unroll
    for (int mi = 0; mi < 2; mi++)
#pragma unroll
        for (int hf = 0; hf < 2; hf++) {
            float v = rmax[mi][hf];
            v = fmaxf(v, __shfl_xor_sync(0xffffffff, v, 1));
            v = fmaxf(v, __shfl_xor_sync(0xffffffff, v, 2));
            if ((lane & 3) == 0)
                red[wn * 128 + wm * 32 + mi * 16 + hf * 8 + (lane >> 2)] = v;
        }
    __syncthreads();

    if (tid < 128) {
        float m = fmaxf(red[tid], red[128 + tid]);
        const float* qr = g_q + ((size_t)bh * TT + m0 + tid) * 64;
        const float* ks = g_ksum + bh * 64;
        float dot = 0.f;
#pragma unroll
        for (int d = 0; d < 64; d++) dot = fmaf(qr[d], ks[d], dot);
        g_sp[bh * TT + m0 + tid] = m - dot * (1.0f / 2048.0f);
    }
}

// =====================================================================
// Kernel 5: approx 40th-largest sparsity per bh
// =====================================================================
__global__ __launch_bounds__(256) void topk40_kernel()
{
    __shared__ float sp[2048];
    __shared__ float rv[256];
    __shared__ int   ri[256];
    const int bh = blockIdx.x, tid = threadIdx.x;
    for (int l = tid; l < 2048; l += 256) sp[l] = g_sp[bh * 2048 + l];
    __syncthreads();
    for (int it = 0; it < TU; it++) {
        float bv = -INFINITY; int bi = 2048;
        for (int l = tid; l < 2048; l += 256) {
            float v = sp[l];
            if (v > bv) { bv = v; bi = l; }
        }
        rv[tid] = bv; ri[tid] = bi;
        __syncthreads();
        for (int s = 128; s > 0; s >>= 1) {
            if (tid < s) {
                float ov = rv[tid + s]; int oi = ri[tid + s];
                if (ov > rv[tid] || (ov == rv[tid] && oi < ri[tid])) { rv[tid] = ov; ri[tid] = oi; }
            }
            __syncthreads();
        }
        if (tid == 0) {
            sp[ri[0]] = -INFINITY;
            if (it == TU - 1) g_s40[bh] = rv[0];
        }
        __syncthreads();
    }
}

// =====================================================================
// Kernel 5b: collect candidates with approx score >= s40 - delta
// =====================================================================
__global__ __launch_bounds__(256) void cand_kernel()
{
    __shared__ int cnt;
    const int bh = blockIdx.x, tid = threadIdx.x;
    if (tid == 0) cnt = 0;
    __syncthreads();
    const float thr = g_s40[bh] - 0.05f;
    for (int l = tid; l < 2048; l += 256) {
        if (g_sp[bh * 2048 + l] >= thr) {
            int p = atomicAdd(&cnt, 1);
            if (p < TCAP) g_cand[bh * TCAP + p] = l;
        }
    }
    __syncthreads();
    if (tid == 0) g_ncand[bh] = (cnt < TCAP) ? cnt : TCAP;
}

// =====================================================================
// Kernel 5c: exact fp32 rescore of candidates
// =====================================================================
__global__ __launch_bounds__(256) void rescore_kernel()
{
    __shared__ float qc[64][68];
    __shared__ float ks[32][68];
    const int bh = blockIdx.x, sp = blockIdx.y, tid = threadIdx.x;
    const int ncand = g_ncand[bh];
    const int c = tid >> 2, l4 = tid & 3;

    for (int c0 = 0; c0 < ncand; c0 += 64) {
        const int nc = min(64, ncand - c0);
        __syncthreads();
        for (int l = tid; l < nc * 16; l += 256) {
            int cc = l >> 4, q4 = l & 15;
            int t = g_cand[bh * TCAP + c0 + cc];
            *(float4*)&qc[cc][q4*4] = *(const float4*)&g_q[((size_t)bh * 2048 + t) * 64 + q4 * 4];
        }
        float m = -INFINITY;
        for (int ch = 0; ch < 8; ch++) {
            const int j0 = sp * 256 + ch * 32;
            __syncthreads();
            for (int l = tid; l < 512; l += 256) {
                int j = l >> 4, q4 = l & 15;
                *(float4*)&ks[j][q4*4] = *(const float4*)&g_ks[((size_t)bh * 2048 + j0 + j) * 64 + q4 * 4];
            }
            __syncthreads();
            if (c < nc) {
#pragma unroll
                for (int kk = 0; kk < 8; kk++) {
                    int j = l4 + kk * 4;
                    float dot = 0.f;
#pragma unroll
                    for (int d = 0; d < 64; d++) dot = fmaf(qc[c][d], ks[j][d], dot);
                    m = fmaxf(m, dot);
                }
            }
        }
        m = fmaxf(m, __shfl_xor_sync(0xffffffff, m, 1));
        m = fmaxf(m, __shfl_xor_sync(0xffffffff, m, 2));
        if (l4 == 0 && c < nc)
            g_rmax[(bh * TCAP + c0 + c) * NSPLIT + sp] = m;
    }
}

// =====================================================================
// Kernel 5d: exact candidate sparsity + exact top-40 (tie: lower t)
// 512 threads to cover TCAP=512 candidates.
// =====================================================================
__global__ __launch_bounds__(512) void final_topk_kernel()
{
    __shared__ float sv[512];
    __shared__ int   st[512];
    __shared__ float rv[512];
    __shared__ int   rs[512];
    __shared__ float sks[64];
    const int bh = blockIdx.x, tid = threadIdx.x;
    const int ncand = g_ncand[bh];
    if (tid < 64) sks[tid] = g_ksum[bh * 64 + tid];
    __syncthreads();

    float val = -INFINITY;
    int t = 0x7fffffff;
    if (tid < ncand) {
        t = g_cand[bh * TCAP + tid];
        float m = -INFINITY;
#pragma unroll
        for (int sp = 0; sp < NSPLIT; sp++)
            m = fmaxf(m, g_rmax[(bh * TCAP + tid) * NSPLIT + sp]);
        const float* qr = g_q + ((size_t)bh * 2048 + t) * 64;
        float dot = 0.f;
#pragma unroll
        for (int d = 0; d < 64; d++) dot = fmaf(qr[d], sks[d], dot);
        val = m - dot * (1.0f / 2048.0f);
    }
    sv[tid] = val; st[tid] = t;
    __syncthreads();

    for (int it = 0; it < TU; it++) {
        rv[tid] = sv[tid]; rs[tid] = tid;
        __syncthreads();
        for (int s = 256; s > 0; s >>= 1) {
            if (tid < s) {
                float ov = rv[tid + s]; int os = rs[tid + s];
                if (ov > rv[tid] || (ov == rv[tid] && st[os] < st[rs[tid]])) { rv[tid] = ov; rs[tid] = os; }
            }
            __syncthreads();
        }
        if (tid == 0) { g_top[bh * TU + it] = st[rs[0]]; sv[rs[0]] = -INFINITY; }
        __syncthreads();
    }
}

// =====================================================================
// Kernel 6: FUSED flash-style attention over 256-key chunks (R12)
// =====================================================================
#define SM_QS 0
#define SM_KV (40*68)
#define SM_E  (40*68 + 64*68)
#define SM_M  (SM_E + 40*256)
#define SM_S  (SM_M + 40)
#define SM_TOT (SM_S + 40)

__global__ __launch_bounds__(256) void attn_fused()
{
    extern __shared__ __align__(16) float fs[];
    const int sp = blockIdx.x, bh = blockIdx.y, tid = threadIdx.x;
    const int j = tid & 63, ig = tid >> 6;

    for (int l = tid; l < 640; l += 256) {
        int i = l >> 4, q4 = l & 15;
        int t = g_top[bh * TU + i];
        *(float4*)&fs[SM_QS + i*68 + q4*4] =
            *(const float4*)&g_q[((size_t)bh * 2048 + t) * 64 + q4 * 4];
    }

    for (int c = 0; c < 4; c++) {
        const int j0 = sp * 256 + c * 64;
        __syncthreads();
        for (int l = tid; l < 1024; l += 256) {
            int jj = l >> 4, q4 = l & 15;
            *(float4*)&fs[SM_KV + jj*68 + q4*4] =
                *(const float4*)&g_k[((size_t)bh * 2048 + j0 + jj) * 64 + q4 * 4];
        }
        __syncthreads();
#pragma unroll
        for (int r = 0; r < 10; r++) {
            const int i = ig * 10 + r;
            float dot = 0.f;
#pragma unroll
            for (int d = 0; d < 64; d++)
                dot = fmaf(fs[SM_QS + i*68 + d], fs[SM_KV + j*68 + d], dot);
            fs[SM_E + i*256 + c*64 + j] = dot;
        }
    }
    __syncthreads();

    if (tid < 40) {
        float m = -INFINITY;
        for (int jj = 0; jj < 256; jj++) m = fmaxf(m, fs[SM_E + tid*256 + jj]);
        fs[SM_M + tid] = m;
    }
    __syncthreads();
    for (int l = tid; l < 10240; l += 256) {
        int i = l >> 8;
        fs[SM_E + l] = expf(fs[SM_E + l] - fs[SM_M + i]);
    }
    __syncthreads();
    if (tid < 40) {
        float s = 0.f;
        for (int jj = 0; jj < 256; jj++) s += fs[SM_E + tid*256 + jj];
        g_pm[(bh * NSPLIT + sp) * TU + tid] = fs[SM_M + tid];
        g_ps[(bh * NSPLIT + sp) * TU + tid] = s;
    }

    float acc[10];
#pragma unroll
    for (int r = 0; r < 10; r++) acc[r] = 0.f;
    for (int c = 0; c < 4; c++) {
        const int j0 = sp * 256 + c * 64;
        __syncthreads();
        for (int l = tid; l < 1024; l += 256) {
            int jj = l >> 4, q4 = l & 15;
            *(float4*)&fs[SM_KV + jj*68 + q4*4] =
                *(const float4*)&g_v[((size_t)bh * 2048 + j0 + jj) * 64 + q4 * 4];
        }
        __syncthreads();
#pragma unroll 4
        for (int jj = 0; jj < 64; jj++) {
            float vv = fs[SM_KV + jj*68 + j];
#pragma unroll
            for (int r = 0; r < 10; r++)
                acc[r] = fmaf(fs[SM_E + (ig*10 + r)*256 + c*64 + jj], vv, acc[r]);
        }
    }
#pragma unroll
    for (int r = 0; r < 10; r++)
        g_pp[((size_t)(bh * NSPLIT + sp) * TU + ig * 10 + r) * 64 + j] = acc[r];
}

__global__ __launch_bounds__(256) void attn_merge()
{
    const int bh = blockIdx.x, tid = threadIdx.x;
    const int d = tid & 63, ii = tid >> 6;
#pragma unroll
    for (int r = 0; r < 10; r++) {
        const int i = ii * 10 + r;
        float M = -INFINITY;
#pragma unroll
        for (int k = 0; k < NSPLIT; k++)
            M = fmaxf(M, g_pm[(bh * NSPLIT + k) * TU + i]);
        float S = 0.f, o = 0.f;
#pragma unroll
        for (int k = 0; k < NSPLIT; k++) {
            float w = expf(g_pm[(bh * NSPLIT + k) * TU + i] - M);
            S = fmaf(g_ps[(bh * NSPLIT + k) * TU + i], w, S);
            o = fmaf(g_pp[((size_t)(bh * NSPLIT + k) * TU + i) * 64 + d], w, o);
        }
        g_attn[(bh * TU + i) * 64 + d] = o / S;
    }
}

// =====================================================================
// Kernel 9: fill merged context with vmean
// =====================================================================
__global__ __launch_bounds__(256) void ctxfill_kernel()
{
    const int idx = blockIdx.x * 256 + threadIdx.x;
    const int m = idx >> 7, nf4 = idx & 127;
    const int b = m >> 11;
    const int h = nf4 >> 4, d0 = (nf4 & 15) * 4;
    float4 v = *(const float4*)&g_vmean[((b << 3) + h) * 64 + d0];
    *(float4*)&g_ctx[(size_t)m * 512 + nf4 * 4] = v;
}

// =====================================================================
// Kernel 10: scatter attention rows into context
// =====================================================================
__global__ void scatter_kernel()
{
    const int bh = blockIdx.x, i = blockIdx.y, d = threadIdx.x;
    const int t = g_top[bh * TU + i];
    const int b = bh >> 3, h = bh & 7;
    g_ctx[(size_t)((b << 11) + t) * 512 + (h << 6) + d] =
        g_attn[(bh * TU + i) * 64 + d];
}

// =====================================================================
// Kernel 11a: base_out[b] = bo + vmean_ctx_row(b) @ Wo^T (GEMV)
// =====================================================================
__global__ __launch_bounds__(128) void base_prep(
    const float* __restrict__ Wo, const float* __restrict__ bo)
{
    __shared__ float bs[512];
    const int b = blockIdx.x, n0 = blockIdx.y * 128, tid = threadIdx.x;
    for (int k = tid; k < 512; k += 128) bs[k] = g_vmean[b * 512 + k];
    __syncthreads();
    const int n = n0 + tid;
    const float* w = Wo + (size_t)n * 512;
    float acc = bo[n];
#pragma unroll 8
    for (int k = 0; k < 512; k++) acc = fmaf(bs[k], w[k], acc);
    g_base_out[b * 512 + n] = acc;
}

// =====================================================================
// Kernel 11b: broadcast-fill output with per-batch base rows
// =====================================================================
__global__ __launch_bounds__(256) void fill_out(float* __restrict__ out)
{
    const int idx = blockIdx.x * 256 + threadIdx.x;
    const int m = idx >> 7, nf4 = idx & 127;
    const int b = m >> 11;
    float4 v = *(const float4*)&g_base_out[b * 512 + nf4 * 4];
    *(float4*)&out[(size_t)m * 512 + nf4 * 4] = v;
}

// =====================================================================
// Kernel 11c: compact output GEMM over the 1280 modified ctx rows
// =====================================================================
__global__ __launch_bounds__(256) void out_gemm_compact(
    const float* __restrict__ Wo, const float* __restrict__ bo,
    float* __restrict__ out)
{
    __shared__ float As[16][132];
    __shared__ float Bs[16][132];
    __shared__ int rowoff[128];
    const int tid = threadIdx.x;
    const int tx = tid & 15, ty = tid >> 4;
    const int m0 = blockIdx.y * 128, n0 = blockIdx.x * 128;

    if (tid < 128) {
        int mr = m0 + tid;
        int bh = mr / TU, i = mr % TU;
        int t = g_top[bh * TU + i];
        rowoff[tid] = ((bh >> 3) << 11) + t;
    }
    __syncthreads();

    float acc[8][8];
#pragma unroll
    for (int r = 0; r < 8; r++)
#pragma unroll
        for (int c = 0; c < 8; c++) acc[r][c] = 0.f;

    for (int kt = 0; kt < 512; kt += 16) {
#pragma unroll
        for (int i = 0; i < 2; i++) {
            int l = tid + i * 256;
            int row = l >> 2, kq = l & 3;
            float4 a = *(const float4*)&g_ctx[(size_t)rowoff[row] * 512 + kt + kq * 4];
            As[kq*4+0][row] = a.x; As[kq*4+1][row] = a.y;
            As[kq*4+2][row] = a.z; As[kq*4+3][row] = a.w;
            float4 b = *(const float4*)&Wo[(size_t)(n0 + row) * 512 + kt + kq * 4];
            Bs[kq*4+0][row] = b.x; Bs[kq*4+1][row] = b.y;
            Bs[kq*4+2][row] = b.z; Bs[kq*4+3][row] = b.w;
        }
        __syncthreads();
#pragma unroll
        for (int k = 0; k < 16; k++) {
            float4 a0 = *(const float4*)&As[k][ty*8];
            float4 a1 = *(const float4*)&As[k][ty*8+4];
            float4 b0 = *(const float4*)&Bs[k][tx*8];
            float4 b1 = *(const float4*)&Bs[k][tx*8+4];
            float ar[8] = {a0.x,a0.y,a0.z,a0.w,a1.x,a1.y,a1.z,a1.w};
            float br[8] = {b0.x,b0.y,b0.z,b0.w,b1.x,b1.y,b1.z,b1.w};
#pragma unroll
            for (int r = 0; r < 8; r++)
#pragma unroll
                for (int c = 0; c < 8; c++)
                    acc[r][c] = fmaf(ar[r], br[c], acc[r][c]);
        }
        __syncthreads();
    }

    const int n = n0 + tx * 8;
#pragma unroll
    for (int r = 0; r < 8; r++) {
        int row = ty * 8 + r;
        float* orow = &out[(size_t)rowoff[row] * 512 + n];
        float4 o0, o1;
        o0.x = acc[r][0] + bo[n+0]; o0.y = acc[r][1] + bo[n+1];
        o0.z = acc[r][2] + bo[n+2]; o0.w = acc[r][3] + bo[n+3];
        o1.x = acc[r][4] + bo[n+4]; o1.y = acc[r][5] + bo[n+5];
        o1.z = acc[r][6] + bo[n+6]; o1.w = acc[r][7] + bo[n+7];
        *(float4*)&orow[0] = o0;
        *(float4*)&orow[4] = o1;
    }
}

// =====================================================================
extern "C" void kernel_launch(void* const* d_in, const int* in_sizes, int n_in,
                              void* d_out, int out_size)
{
    const float* hs = (const float*)d_in[0];
    const int*  idx = (const int*)  d_in[1];
    const float* Wq = (const float*)d_in[2]; const float* bq = (const float*)d_in[3];
    const float* Wk = (const float*)d_in[4]; const float* bk = (const float*)d_in[5];
    const float* Wv = (const float*)d_in[6]; const float* bv = (const float*)d_in[7];
    const float* Wo = (const float*)d_in[8]; const float* bo = (const float*)d_in[9];
    float* out = (float*)d_out;

    cudaFuncSetAttribute(sparsity_mma, cudaFuncAttributeMaxDynamicSharedMemorySize, 38912);
    cudaFuncSetAttribute(attn_fused, cudaFuncAttributeMaxDynamicSharedMemorySize, SM_TOT * 4);

    qkv_gemm     <<<dim3(4, 64, 3), 256>>>(hs, Wq, bq, Wk, bk, Wv, bv);
    gather_kernel<<<dim3(32, 8), 256>>>(idx);
    stats_part   <<<dim3(32, 2, 8), 256>>>();
    stats_merge  <<<dim3(32, 2), 64>>>();
    sparsity_mma <<<dim3(16, 32), 256, 38912>>>();
    topk40_kernel<<<32, 256>>>();
    cand_kernel  <<<32, 256>>>();
    rescore_kernel<<<dim3(32, NSPLIT), 256>>>();
    final_topk_kernel<<<32, 512>>>();
    attn_fused   <<<dim3(NSPLIT, 32), 256, SM_TOT * 4>>>();
    attn_merge   <<<32, 256>>>();
    ctxfill_kernel<<<4096, 256>>>();
    scatter_kernel<<<dim3(32, TU), 64>>>();
    base_prep    <<<dim3(TB, 4), 128>>>(Wo, bo);
    fill_out     <<<4096, 256>>>(out);
    out_gemm_compact<<<dim3(4, 10), 256>>>(Wo, bo, out);
}